// round 16
// baseline (speedup 1.0000x reference)
#include <cuda_runtime.h>
#include <cuda_fp16.h>
#include <mma.h>
#include <math.h>

using namespace nvcuda;

// Problem dims
#define CB  8
#define CS  1300
#define CD  1080
#define CH  12
#define CDK 90
#define CDP 96
#define CFF 3240
#define CBS (CB*CS)

// ---------------- scratch ----------------
__device__ half  g_x2h [(size_t)CBS*CD];
__device__ half  g_qkvh[(size_t)CBS*CFF];
__device__ half  g_h1h [(size_t)CBS*CFF];
__device__ half  g_attnh[(size_t)CBS*CD];
__device__ half  g_qhh[(size_t)CB*CH*CS*CDP];
__device__ half  g_khh[(size_t)CB*CH*CS*CDP];
__device__ half  g_vhh[(size_t)CB*CH*CS*CDP];
__device__ float g_res[(size_t)CBS*CD];
__device__ half  g_wqkvh[(size_t)CD*CFF];
__device__ float g_bqkv[CFF];
__device__ half  g_wrh [(size_t)11664000];
#define WR_WO 0
#define WR_W1 1166400
#define WR_W3 4665600
#define WR_W2 8164800

enum { EPI_NONE=0, EPI_SCALE=1, EPI_BIAS=2, EPI_BIAS_RES=3, EPI_SWIGLU=4 };

__device__ __forceinline__ void cp_async16(void* smem, const void* gmem, bool pred)
{
    unsigned saddr = (unsigned)__cvta_generic_to_shared(smem);
    int sz = pred ? 16 : 0;
    asm volatile("cp.async.cg.shared.global [%0], [%1], 16, %2;\n"
                 :: "r"(saddr), "l"(gmem), "r"(sz));
}
__device__ __forceinline__ void cp_commit() { asm volatile("cp.async.commit_group;\n"); }

__device__ __forceinline__ void mma_f16(float* d,
    unsigned a0, unsigned a1, unsigned a2, unsigned a3,
    unsigned b0, unsigned b1)
{
    asm volatile("mma.sync.aligned.m16n8k16.row.col.f32.f16.f16.f32 "
                 "{%0,%1,%2,%3}, {%4,%5,%6,%7}, {%8,%9}, {%0,%1,%2,%3};"
                 : "+f"(d[0]), "+f"(d[1]), "+f"(d[2]), "+f"(d[3])
                 : "r"(a0), "r"(a1), "r"(a2), "r"(a3), "r"(b0), "r"(b1));
}

__device__ __forceinline__ void ldsm4t(unsigned& r0, unsigned& r1,
                                       unsigned& r2, unsigned& r3, const half* p)
{
    unsigned addr = (unsigned)__cvta_generic_to_shared(p);
    asm volatile("ldmatrix.sync.aligned.m8n8.x4.trans.shared.b16 {%0,%1,%2,%3}, [%4];"
                 : "=r"(r0), "=r"(r1), "=r"(r2), "=r"(r3) : "r"(addr));
}

__device__ __forceinline__ void store4(float* p, float4 v)
{
    *reinterpret_cast<float4*>(p) = v;
}
__device__ __forceinline__ void store4(half* p, float4 v)
{
    half2* h = reinterpret_cast<half2*>(p);
    h[0] = __floats2half2_rn(v.x, v.y);
    h[1] = __floats2half2_rn(v.z, v.w);
}
__device__ __forceinline__ float4 load4aux(const float* p)
{
    return *reinterpret_cast<const float4*>(p);
}
__device__ __forceinline__ float4 load4aux(const half* p)
{
    const half2* h = reinterpret_cast<const half2*>(p);
    float2 a = __half22float2(h[0]);
    float2 b = __half22float2(h[1]);
    return make_float4(a.x, a.y, b.x, b.y);
}

// ------ FP16 GEMM: 128x128 tile, 32x64 warp tile, BK=64, 3-stage, 2 CTA/SM --
#define ALDH 72                     // halfs per A row (64 + 8 pad)
#define BLDH 136                    // halfs per B row (128 + 8 pad)
#define CLD 24
#define STG_A_H (128*ALDH)          // 9216 halfs
#define STG_B_H (64*BLDH)           // 8704 halfs
#define STG_H (STG_A_H+STG_B_H)     // 17920 halfs / stage
#define SMEM_BYTES (3*STG_H*2)      // 107520 B

template<int EPI, typename OutT, typename AuxT>
__global__ __launch_bounds__(256, 2)
void gemm_h(const half* __restrict__ A, int lda,
            const half* __restrict__ Bm, int ldb,
            OutT* __restrict__ C, int ldc,
            const float* __restrict__ bias,
            const AuxT* __restrict__ aux, int ldx,
            int M, int N, int K)
{
    const int m0 = blockIdx.y * 128;
    const int n0 = blockIdx.x * 128;
    const int kEnd  = K;
    const int nIter = (kEnd + 63) >> 6;

    extern __shared__ __align__(16) char smem_raw[];
    half* smem_h = reinterpret_cast<half*>(smem_raw);

    const int tid = threadIdx.x;
    const int wid = tid >> 5;
    const int lane = tid & 31;
    const int warp_m = wid & 3;
    const int warp_n = wid >> 2;

    // A: 128 rows x 64 halfs = 1024 x 16B chunks; 4 chunks/thread
    const int aRow = tid >> 1;          // 0..127
    const int aC0  = (tid & 1) * 32;    // 0 or 32
    // B: 64 rows x 128 halfs = 1024 chunks; 4 chunks/thread
    const int bRow = tid >> 2;          // 0..63
    const int bC0  = (tid & 3) * 32;    // 0..96

    const bool aRowOk = (m0 + aRow) < M;
    const half* aBase = A + (long)(m0 + aRow) * lda + aC0;
    const half* bBase = Bm + (long)bRow * ldb + n0 + bC0;
    bool bColOk[4];
    #pragma unroll
    for (int c = 0; c < 4; c++) bColOk[c] = (n0 + bC0 + 8 * c) < N;

    wmma::fragment<wmma::accumulator, 16, 16, 16, float> acc[2][4];
    #pragma unroll
    for (int i = 0; i < 2; i++)
        #pragma unroll
        for (int j = 0; j < 4; j++) wmma::fill_fragment(acc[i][j], 0.f);

    auto issue = [&](int it, int buf) {
        const int k0 = it << 6;
        half* as = smem_h + buf * STG_H;
        half* bs = as + STG_A_H;
        #pragma unroll
        for (int c = 0; c < 4; c++)
            cp_async16(&as[aRow * ALDH + aC0 + 8 * c], aBase + k0 + 8 * c,
                       aRowOk && (k0 + aC0 + 8 * c < kEnd));
        const bool rOk = (k0 + bRow) < kEnd;
        #pragma unroll
        for (int c = 0; c < 4; c++)
            cp_async16(&bs[bRow * BLDH + bC0 + 8 * c], bBase + (long)k0 * ldb + 8 * c,
                       rOk && bColOk[c]);
    };

    issue(0, 0); cp_commit();
    if (nIter > 1) { issue(1, 1); cp_commit(); }

    for (int it = 0; it < nIter; it++) {
        const int buf = it % 3;
        if (it + 1 < nIter) asm volatile("cp.async.wait_group 1;\n");
        else                asm volatile("cp.async.wait_group 0;\n");
        __syncthreads();
        if (it + 2 < nIter) { issue(it + 2, (it + 2) % 3); cp_commit(); }

        const half* as = smem_h + buf * STG_H;
        const half* bs = as + STG_A_H;
        #pragma unroll
        for (int kk = 0; kk < 64; kk += 16) {
            wmma::fragment<wmma::matrix_a, 16, 16, 16, half, wmma::row_major> af[2];
            #pragma unroll
            for (int i = 0; i < 2; i++)
                wmma::load_matrix_sync(af[i], &as[(warp_m * 32 + i * 16) * ALDH + kk], ALDH);
            #pragma unroll
            for (int j = 0; j < 4; j++) {
                wmma::fragment<wmma::matrix_b, 16, 16, 16, half, wmma::row_major> bf;
                wmma::load_matrix_sync(bf, &bs[kk * BLDH + warp_n * 64 + j * 16], BLDH);
                wmma::mma_sync(acc[0][j], af[0], bf, acc[0][j]);
                wmma::mma_sync(acc[1][j], af[1], bf, acc[1][j]);
            }
        }
        // no bottom sync: issue(it+2) targets the buffer consumed at it-1,
        // fenced by this iteration's top sync
    }
    __syncthreads();   // protect smem reuse by epilogue stage

    float* fstage = reinterpret_cast<float*>(smem_raw) + wid * 16 * CLD;
    const int er  = lane >> 1;
    const int ec0 = (lane & 1) * 8;
    #pragma unroll
    for (int i = 0; i < 2; i++) {
        #pragma unroll
        for (int j = 0; j < 4; j++) {
            wmma::store_matrix_sync(fstage, acc[i][j], CLD, wmma::mem_row_major);
            __syncwarp();
            const int gr = m0 + warp_m * 32 + i * 16 + er;
            const int gcb = n0 + warp_n * 64 + j * 16 + ec0;
            if (gr < M) {
                #pragma unroll
                for (int h4 = 0; h4 < 2; h4++) {
                    const int gc = gcb + h4 * 4;
                    if (gc + 3 < N) {
                        float4 v = *reinterpret_cast<const float4*>(&fstage[er * CLD + ec0 + h4 * 4]);
                        if (EPI == EPI_BIAS) {
                            float4 bv = *reinterpret_cast<const float4*>(&bias[gc]);
                            v.x += bv.x; v.y += bv.y; v.z += bv.z; v.w += bv.w;
                        }
                        if (EPI == EPI_BIAS_RES) {
                            float4 bv = *reinterpret_cast<const float4*>(&bias[gc]);
                            float4 av = load4aux(&aux[(long)gr * ldx + gc]);
                            v.x += bv.x + av.x; v.y += bv.y + av.y;
                            v.z += bv.z + av.z; v.w += bv.w + av.w;
                        }
                        if (EPI == EPI_SWIGLU) {
                            float4 bv = *reinterpret_cast<const float4*>(&bias[gc]);
                            float4 hv = load4aux(&aux[(long)gr * ldx + gc]);
                            v.x = (hv.x / (1.f + __expf(-hv.x))) * (v.x + bv.x);
                            v.y = (hv.y / (1.f + __expf(-hv.y))) * (v.y + bv.y);
                            v.z = (hv.z / (1.f + __expf(-hv.z))) * (v.z + bv.z);
                            v.w = (hv.w / (1.f + __expf(-hv.w))) * (v.w + bv.w);
                        }
                        store4(&C[(long)gr * ldc + gc], v);
                    }
                }
            }
            __syncwarp();
        }
    }
}

// ------------- flash attention: fp16 m16n8k16, ldmatrix.trans PV -----------
#define FQ 128
#define FN 64
#define QLDH 104
#define FLASH_SMEM ((FQ*QLDH + 2*FN*QLDH)*2)   // 53248 B

__global__ __launch_bounds__(256, 2)
void flash_k(const half* __restrict__ qh, const half* __restrict__ kh,
             const half* __restrict__ vh, half* __restrict__ attn, float iscale)
{
    const int zi = blockIdx.y;
    const int iT = (int)gridDim.x - 1 - (int)blockIdx.x;
    const int i0 = iT * FQ;
    const int tid = threadIdx.x;
    const int wid = tid >> 5;
    const int lane = tid & 31;
    const int g = lane >> 2;
    const int t = lane & 3;

    const half* Qp = qh + (long)zi * CS * CDP;
    const half* Kp = kh + (long)zi * CS * CDP;
    const half* Vp = vh + (long)zi * CS * CDP;

    extern __shared__ __align__(16) half smh[];
    half* Qs = smh;
    half* Ks = smh + FQ * QLDH;
    half* Vs = Ks + FN * QLDH;

    for (int tt = tid; tt < FQ * 12; tt += 256) {
        int r = tt / 12, c8 = (tt % 12) * 8;
        cp_async16(&Qs[r * QLDH + c8], Qp + (long)(i0 + r) * CDP + c8, (i0 + r) < CS);
    }
    cp_commit();

    float oacc[12][4];
    #pragma unroll
    for (int n = 0; n < 12; n++)
        #pragma unroll
        for (int s = 0; s < 4; s++) oacc[n][s] = 0.f;
    float m0 = -1e30f, m1 = -1e30f, l0 = 0.f, l1 = 0.f;

    const int rw = wid * 16;
    const int row0 = i0 + rw + g;
    const int row1 = row0 + 8;
    const int jn = (min(CS, i0 + FQ) + FN - 1) / FN;

    asm volatile("cp.async.wait_group 0;\n");
    __syncthreads();

    for (int j = 0; j < jn; j++) {
        const int j0 = j * FN;
        __syncthreads();
        for (int tt = tid; tt < FN * 12; tt += 256) {
            int r = tt / 12, c8 = (tt % 12) * 8;
            cp_async16(&Ks[r * QLDH + c8], Kp + (long)(j0 + r) * CDP + c8, (j0 + r) < CS);
        }
        cp_commit();
        for (int tt = tid; tt < FN * 12; tt += 256) {
            int r = tt / 12, c8 = (tt % 12) * 8;
            cp_async16(&Vs[r * QLDH + c8], Vp + (long)(j0 + r) * CDP + c8, (j0 + r) < CS);
        }
        cp_commit();
        asm volatile("cp.async.wait_group 1;\n");
        __syncthreads();

        const bool active = (j0 <= i0 + rw + 15);
        float sacc[8][4];

        if (active) {
            #pragma unroll
            for (int n = 0; n < 8; n++)
                #pragma unroll
                for (int s = 0; s < 4; s++) sacc[n][s] = 0.f;

            #pragma unroll
            for (int kf = 0; kf < 6; kf++) {
                const int kc = kf * 16;
                unsigned a0 = *reinterpret_cast<const unsigned*>(&Qs[(rw + g)     * QLDH + kc + 2 * t]);
                unsigned a1 = *reinterpret_cast<const unsigned*>(&Qs[(rw + g + 8) * QLDH + kc + 2 * t]);
                unsigned a2 = *reinterpret_cast<const unsigned*>(&Qs[(rw + g)     * QLDH + kc + 2 * t + 8]);
                unsigned a3 = *reinterpret_cast<const unsigned*>(&Qs[(rw + g + 8) * QLDH + kc + 2 * t + 8]);
                #pragma unroll
                for (int nf = 0; nf < 8; nf++) {
                    unsigned b0 = *reinterpret_cast<const unsigned*>(&Ks[(nf * 8 + g) * QLDH + kc + 2 * t]);
                    unsigned b1 = *reinterpret_cast<const unsigned*>(&Ks[(nf * 8 + g) * QLDH + kc + 2 * t + 8]);
                    mma_f16(sacc[nf], a0, a1, a2, a3, b0, b1);
                }
            }

            float rmax0 = -1e30f, rmax1 = -1e30f;
            #pragma unroll
            for (int nf = 0; nf < 8; nf++) {
                const int c0 = j0 + nf * 8 + 2 * t;
                float s0 = sacc[nf][0] * iscale; if (c0     > row0) s0 = -1e30f;
                float s1 = sacc[nf][1] * iscale; if (c0 + 1 > row0) s1 = -1e30f;
                float s2 = sacc[nf][2] * iscale; if (c0     > row1) s2 = -1e30f;
                float s3 = sacc[nf][3] * iscale; if (c0 + 1 > row1) s3 = -1e30f;
                sacc[nf][0] = s0; sacc[nf][1] = s1; sacc[nf][2] = s2; sacc[nf][3] = s3;
                rmax0 = fmaxf(rmax0, fmaxf(s0, s1));
                rmax1 = fmaxf(rmax1, fmaxf(s2, s3));
            }
            rmax0 = fmaxf(rmax0, __shfl_xor_sync(0xffffffffu, rmax0, 1));
            rmax0 = fmaxf(rmax0, __shfl_xor_sync(0xffffffffu, rmax0, 2));
            rmax1 = fmaxf(rmax1, __shfl_xor_sync(0xffffffffu, rmax1, 1));
            rmax1 = fmaxf(rmax1, __shfl_xor_sync(0xffffffffu, rmax1, 2));

            const float mn0 = fmaxf(m0, rmax0);
            const float mn1 = fmaxf(m1, rmax1);
            const float al0 = __expf(m0 - mn0);
            const float al1 = __expf(m1 - mn1);
            float ps0 = 0.f, ps1 = 0.f;
            #pragma unroll
            for (int nf = 0; nf < 8; nf++) {
                float p0 = __half2float(__float2half_rn(__expf(sacc[nf][0] - mn0)));
                float p1 = __half2float(__float2half_rn(__expf(sacc[nf][1] - mn0)));
                float p2 = __half2float(__float2half_rn(__expf(sacc[nf][2] - mn1)));
                float p3 = __half2float(__float2half_rn(__expf(sacc[nf][3] - mn1)));
                sacc[nf][0] = p0; sacc[nf][1] = p1; sacc[nf][2] = p2; sacc[nf][3] = p3;
                ps0 += p0 + p1; ps1 += p2 + p3;
            }
            ps0 += __shfl_xor_sync(0xffffffffu, ps0, 1);
            ps0 += __shfl_xor_sync(0xffffffffu, ps0, 2);
            ps1 += __shfl_xor_sync(0xffffffffu, ps1, 1);
            ps1 += __shfl_xor_sync(0xffffffffu, ps1, 2);
            l0 = l0 * al0 + ps0;  m0 = mn0;
            l1 = l1 * al1 + ps1;  m1 = mn1;

            #pragma unroll
            for (int n = 0; n < 12; n++) {
                oacc[n][0] *= al0; oacc[n][1] *= al0;
                oacc[n][2] *= al1; oacc[n][3] *= al1;
            }
        }

        asm volatile("cp.async.wait_group 0;\n");
        __syncthreads();

        if (active) {
            #pragma unroll
            for (int kf = 0; kf < 4; kf++) {
                const int kc = kf * 16;
                half2 h0 = __floats2half2_rn(sacc[2*kf][0],     sacc[2*kf][1]);
                half2 h1 = __floats2half2_rn(sacc[2*kf][2],     sacc[2*kf][3]);
                half2 h2 = __floats2half2_rn(sacc[2*kf + 1][0], sacc[2*kf + 1][1]);
                half2 h3 = __floats2half2_rn(sacc[2*kf + 1][2], sacc[2*kf + 1][3]);
                unsigned a0 = *reinterpret_cast<unsigned*>(&h0);
                unsigned a1 = *reinterpret_cast<unsigned*>(&h1);
                unsigned a2 = *reinterpret_cast<unsigned*>(&h2);
                unsigned a3 = *reinterpret_cast<unsigned*>(&h3);
                const half* vrow = &Vs[(kc + (lane & 15)) * QLDH + 8 * (lane >> 4)];
                #pragma unroll
                for (int nfp = 0; nfp < 6; nfp++) {
                    unsigned b0a, b1a, b0b, b1b;
                    ldsm4t(b0a, b1a, b0b, b1b, vrow + nfp * 16);
                    mma_f16(oacc[2 * nfp],     a0, a1, a2, a3, b0a, b1a);
                    mma_f16(oacc[2 * nfp + 1], a0, a1, a2, a3, b0b, b1b);
                }
            }
        }
    }

    const int b = zi / CH, h = zi - b * CH;
    const float il0 = (l0 > 0.f) ? 1.f / l0 : 0.f;
    const float il1 = (l1 > 0.f) ? 1.f / l1 : 0.f;
    #pragma unroll
    for (int nf = 0; nf < 12; nf++) {
        const int c0 = nf * 8 + 2 * t;
        if (c0 < CDK) {
            if (row0 < CS) {
                half2 v = __floats2half2_rn(oacc[nf][0] * il0, oacc[nf][1] * il0);
                *reinterpret_cast<half2*>(&attn[((long)b * CS + row0) * CD + h * CDK + c0]) = v;
            }
            if (row1 < CS) {
                half2 v = __floats2half2_rn(oacc[nf][2] * il1, oacc[nf][3] * il1);
                *reinterpret_cast<half2*>(&attn[((long)b * CS + row1) * CD + h * CDK + c0]) = v;
            }
        }
    }
}

// -------- single-launch f32 -> fp16 conversion for all 4 weights ------------
__global__ __launch_bounds__(256)
void cvt_all_k(const float* __restrict__ Wo, const float* __restrict__ W1,
               const float* __restrict__ W3, const float* __restrict__ W2,
               half* __restrict__ d)
{
    const int N_WO = 291600, N_W1 = 874800;
    int i = blockIdx.x * 256 + threadIdx.x;
    const float* s;
    size_t off;
    if (i < N_WO)                   { s = Wo; off = 0;                  }
    else if (i < N_WO + N_W1)       { s = W1; off = N_WO;               }
    else if (i < N_WO + 2 * N_W1)   { s = W3; off = N_WO + N_W1;        }
    else if (i < N_WO + 3 * N_W1)   { s = W2; off = N_WO + 2 * N_W1;    }
    else return;
    size_t li = i - off;
    float4 v = reinterpret_cast<const float4*>(s)[li];
    half2* p = reinterpret_cast<half2*>(d + (off + li) * 4);
    p[0] = __floats2half2_rn(v.x, v.y);
    p[1] = __floats2half2_rn(v.z, v.w);
}

// ---------------- pack Wq|Wk|Wv -> fp16 [1080][3240] ----------------
__global__ __launch_bounds__(256)
void pack_qkv_k(const float* __restrict__ Wq, const float* __restrict__ Wk,
                const float* __restrict__ Wv,
                const float* __restrict__ bq, const float* __restrict__ bk,
                const float* __restrict__ bv,
                half* __restrict__ W, float* __restrict__ b)
{
    const int NW4 = CD * (CD / 4);
    long idx = (long)blockIdx.x * 256 + threadIdx.x;
    if (idx < NW4) {
        int r = (int)(idx / (CD / 4));
        int c = (int)(idx % (CD / 4)) * 4;
        float4 vq = *reinterpret_cast<const float4*>(Wq + (long)r * CD + c);
        float4 vk = *reinterpret_cast<const float4*>(Wk + (long)r * CD + c);
        float4 vv = *reinterpret_cast<const float4*>(Wv + (long)r * CD + c);
        half2* pq = reinterpret_cast<half2*>(W + (long)r * CFF + c);
        half2* pk = reinterpret_cast<half2*>(W + (long)r * CFF + CD + c);
        half2* pv = reinterpret_cast<half2*>(W + (long)r * CFF + 2 * CD + c);
        pq[0] = __floats2half2_rn(vq.x, vq.y); pq[1] = __floats2half2_rn(vq.z, vq.w);
        pk[0] = __floats2half2_rn(vk.x, vk.y); pk[1] = __floats2half2_rn(vk.z, vk.w);
        pv[0] = __floats2half2_rn(vv.x, vv.y); pv[1] = __floats2half2_rn(vv.z, vv.w);
    } else if (idx < NW4 + CD / 4) {
        int c = (int)(idx - NW4) * 4;
        *reinterpret_cast<float4*>(b + c)          = *reinterpret_cast<const float4*>(bq + c);
        *reinterpret_cast<float4*>(b + CD + c)     = *reinterpret_cast<const float4*>(bk + c);
        *reinterpret_cast<float4*>(b + 2 * CD + c) = *reinterpret_cast<const float4*>(bv + c);
    }
}

// ---------------- layernorm (vectorized) -> fp16 output ----------------
__global__ __launch_bounds__(256)
void ln_k(const float* __restrict__ x, const float* __restrict__ g,
          const float* __restrict__ b, half* __restrict__ y)
{
    const long row = blockIdx.x;
    const float* xr = x + row * CD;
    half* yr = y + row * CD;
    const int tid = threadIdx.x;

    // 270 float4 per row: thread i handles chunk i (all) and i+256 (i<14)
    float4 v0 = reinterpret_cast<const float4*>(xr)[tid];
    float4 v1 = make_float4(0.f, 0.f, 0.f, 0.f);
    const bool has2 = (tid + 256) < (CD / 4);
    if (has2) v1 = reinterpret_cast<const float4*>(xr)[tid + 256];

    float s  = v0.x + v0.y + v0.z + v0.w + v1.x + v1.y + v1.z + v1.w;
    float s2 = v0.x*v0.x + v0.y*v0.y + v0.z*v0.z + v0.w*v0.w
             + v1.x*v1.x + v1.y*v1.y + v1.z*v1.z + v1.w*v1.w;

    __shared__ float rs[8], rs2[8];
    __shared__ float bm, br;
    #pragma unroll
    for (int o = 16; o; o >>= 1) {
        s  += __shfl_xor_sync(0xffffffffu, s,  o);
        s2 += __shfl_xor_sync(0xffffffffu, s2, o);
    }
    if ((tid & 31) == 0) { rs[tid >> 5] = s; rs2[tid >> 5] = s2; }
    __syncthreads();
    if (tid < 8) {
        float a = rs[tid], a2 = rs2[tid];
        #pragma unroll
        for (int o = 4; o; o >>= 1) {
            a  += __shfl_xor_sync(0xffu, a,  o);
            a2 += __shfl_xor_sync(0xffu, a2, o);
        }
        if (tid == 0) {
            float mean = a / CD;
            float var  = a2 / CD - mean * mean;
            bm = mean;
            br = rsqrtf(var + 1e-5f);
        }
    }
    __syncthreads();
    const float mean = bm, rstd = br;

    {
        float4 gv = reinterpret_cast<const float4*>(g)[tid];
        float4 bv = reinterpret_cast<const float4*>(b)[tid];
        float4 o;
        o.x = (v0.x - mean) * rstd * gv.x + bv.x;
        o.y = (v0.y - mean) * rstd * gv.y + bv.y;
        o.z = (v0.z - mean) * rstd * gv.z + bv.z;
        o.w = (v0.w - mean) * rstd * gv.w + bv.w;
        store4(&yr[tid * 4], o);
    }
    if (has2) {
        float4 gv = reinterpret_cast<const float4*>(g)[tid + 256];
        float4 bv = reinterpret_cast<const float4*>(b)[tid + 256];
        float4 o;
        o.x = (v1.x - mean) * rstd * gv.x + bv.x;
        o.y = (v1.y - mean) * rstd * gv.y + bv.y;
        o.z = (v1.z - mean) * rstd * gv.z + bv.z;
        o.w = (v1.w - mean) * rstd * gv.w + bv.w;
        store4(&yr[(tid + 256) * 4], o);
    }
}

// -------- RoPE + repack from fp16 fused QKV to fp16 [B*H, S, 96] ------------
__global__ __launch_bounds__(256)
void rope_repack_k(const half* __restrict__ qkv,
                   const float* __restrict__ ct, const float* __restrict__ st,
                   half* __restrict__ qh, half* __restrict__ kh,
                   half* __restrict__ vh)
{
    const long total = (long)CB * CH * CS * 48;
    long idx = (long)blockIdx.x * 256 + threadIdx.x;
    if (idx >= total) return;
    const int d = (int)(idx % 48);  idx /= 48;
    const int s = (int)(idx % CS);  idx /= CS;
    const int h = (int)(idx % CH);
    const int b = (int)(idx / CH);

    const long src = ((long)b * CS + s) * CFF + h * CDK;
    const long dst = (((long)b * CH + h) * CS + s) * CDP;

    if (d < 45) {
        const float c1 = ct[s * CDK + d],      s1 = st[s * CDK + d];
        const float c2 = ct[s * CDK + d + 45], s2 = st[s * CDK + d + 45];
        float q1 = __half2float(qkv[src + d]),      q2 = __half2float(qkv[src + d + 45]);
        qh[dst + d]      = __float2half(q1 * c1 - q2 * s1);
        qh[dst + d + 45] = __float2half(q2 * c2 + q1 * s2);
        float k1 = __half2float(qkv[src + CD + d]), k2 = __half2float(qkv[src + CD + d + 45]);
        kh[dst + d]      = __float2half(k1 * c1 - k2 * s1);
        kh[dst + d + 45] = __float2half(k2 * c2 + k1 * s2);
        vh[dst + d]      = qkv[src + 2 * CD + d];
        vh[dst + d + 45] = qkv[src + 2 * CD + d + 45];
    } else {
        const int p = 90 + 2 * (d - 45);
        qh[dst + p] = __float2half(0.f); qh[dst + p + 1] = __float2half(0.f);
        kh[dst + p] = __float2half(0.f); kh[dst + p + 1] = __float2half(0.f);
        vh[dst + p] = __float2half(0.f); vh[dst + p + 1] = __float2half(0.f);
    }
}

// ---------------- host launch ----------------
extern "C" void kernel_launch(void* const* d_in, const int* in_sizes, int n_in,
                              void* d_out, int out_size)
{
    const float* x    = (const float*)d_in[0];
    const float* Wq   = (const float*)d_in[2];
    const float* bq   = (const float*)d_in[3];
    const float* Wk   = (const float*)d_in[4];
    const float* bk   = (const float*)d_in[5];
    const float* Wv   = (const float*)d_in[6];
    const float* bv   = (const float*)d_in[7];
    const float* Wo   = (const float*)d_in[8];
    const float* bo   = (const float*)d_in[9];
    const float* W1   = (const float*)d_in[10];
    const float* b1   = (const float*)d_in[11];
    const float* W2   = (const float*)d_in[12];
    const float* b2   = (const float*)d_in[13];
    const float* W3   = (const float*)d_in[14];
    const float* b3   = (const float*)d_in[15];
    const float* ln1g = (const float*)d_in[16];
    const float* ln1b = (const float*)d_in[17];
    const float* ln2g = (const float*)d_in[18];
    const float* ln2b = (const float*)d_in[19];
    const float* rc   = (const float*)d_in[20];
    const float* rs   = (const float*)d_in[21];
    float* out = (float*)d_out;

    half *x2h, *qkvh, *h1h, *attnh, *wqkvh, *wrh, *qhh, *khh, *vhh;
    float *res, *bqkv;
    cudaGetSymbolAddress((void**)&x2h,   g_x2h);
    cudaGetSymbolAddress((void**)&qkvh,  g_qkvh);
    cudaGetSymbolAddress((void**)&h1h,   g_h1h);
    cudaGetSymbolAddress((void**)&attnh, g_attnh);
    cudaGetSymbolAddress((void**)&qhh,   g_qhh);
    cudaGetSymbolAddress((void**)&khh,   g_khh);
    cudaGetSymbolAddress((void**)&vhh,   g_vhh);
    cudaGetSymbolAddress((void**)&res,   g_res);
    cudaGetSymbolAddress((void**)&wqkvh, g_wqkvh);
    cudaGetSymbolAddress((void**)&bqkv,  g_bqkv);
    cudaGetSymbolAddress((void**)&wrh,   g_wrh);

    cudaFuncSetAttribute((const void*)gemm_h<EPI_BIAS, half, float>,
                         cudaFuncAttributeMaxDynamicSharedMemorySize, SMEM_BYTES);
    cudaFuncSetAttribute((const void*)gemm_h<EPI_BIAS_RES, float, float>,
                         cudaFuncAttributeMaxDynamicSharedMemorySize, SMEM_BYTES);
    cudaFuncSetAttribute((const void*)gemm_h<EPI_SWIGLU, half, half>,
                         cudaFuncAttributeMaxDynamicSharedMemorySize, SMEM_BYTES);
    cudaFuncSetAttribute((const void*)flash_k,
                         cudaFuncAttributeMaxDynamicSharedMemorySize, FLASH_SMEM);

    const float iscale = 1.f / sqrtf((float)CDK);

    // 0) fp16 weights (single launch) + pack QKV
    cvt_all_k<<<(2916000 + 255) / 256, 256>>>(Wo, W1, W3, W2, wrh);
    {
        int total = CD * (CD / 4) + CD / 4;
        pack_qkv_k<<<(total + 255) / 256, 256>>>(Wq, Wk, Wv, bq, bk, bv, wqkvh, bqkv);
    }

    // 1) LN1 -> fp16
    ln_k<<<CBS, 256>>>(x, ln1g, ln1b, x2h);

    // 2) fused QKV projection
    dim3 gQKV((CFF + 127) / 128, (CBS + 127) / 128, 1);
    gemm_h<EPI_BIAS, half, float><<<gQKV, 256, SMEM_BYTES>>>(
        x2h, CD, wqkvh, CFF, qkvh, CFF, bqkv, (const float*)nullptr, 0, CBS, CFF, CD);

    // 3) RoPE + repack
    {
        long total = (long)CB * CH * CS * 48;
        rope_repack_k<<<(unsigned)((total + 255) / 256), 256>>>(qkvh, rc, rs, qhh, khh, vhh);
    }

    // 4) flash attention
    {
        dim3 g((CS + FQ - 1) / FQ, CB * CH);
        flash_k<<<g, 256, FLASH_SMEM>>>(qhh, khh, vhh, attnh, iscale);
    }

    // 5) O-projection + bias + residual(x) -> f32 res
    dim3 gD((CD + 127) / 128, (CBS + 127) / 128, 1);
    gemm_h<EPI_BIAS_RES, float, float><<<gD, 256, SMEM_BYTES>>>(
        attnh, CD, wrh + WR_WO, CD, res, CD, bo, x, CD, CBS, CD, CD);

    // 6) LN2 -> fp16
    ln_k<<<CBS, 256>>>(res, ln2g, ln2b, x2h);

    // 7) h1 = x2@W1 + b1
    dim3 gF((CFF + 127) / 128, (CBS + 127) / 128, 1);
    gemm_h<EPI_BIAS, half, float><<<gF, 256, SMEM_BYTES>>>(
        x2h, CD, wrh + WR_W1, CFF, h1h, CFF, b1, (const float*)nullptr, 0, CBS, CFF, CD);

    // 8) h1 = silu(h1) * (x2@W3 + b3)
    gemm_h<EPI_SWIGLU, half, half><<<gF, 256, SMEM_BYTES>>>(
        x2h, CD, wrh + WR_W3, CFF, h1h, CFF, b3, h1h, CFF, CBS, CFF, CD);

    // 9) out = res + h1@W2 + b2
    gemm_h<EPI_BIAS_RES, float, float><<<gD, 256, SMEM_BYTES>>>(
        h1h, CFF, wrh + WR_W2, CD, out, CD, b2, res, CD, CBS, CD, CFF);
}

// round 17
// speedup vs baseline: 1.1710x; 1.1710x over previous
#include <cuda_runtime.h>
#include <cuda_fp16.h>
#include <mma.h>
#include <math.h>

using namespace nvcuda;

// Problem dims
#define CB  8
#define CS  1300
#define CD  1080
#define CH  12
#define CDK 90
#define CDP 96
#define CFF 3240
#define CBS (CB*CS)

// ---------------- scratch ----------------
__device__ half  g_x2h [(size_t)CBS*CD];
__device__ half  g_qkvh[(size_t)CBS*CFF];
__device__ half  g_h1h [(size_t)CBS*CFF];
__device__ half  g_attnh[(size_t)CBS*CD];
__device__ half  g_qhh[(size_t)CB*CH*CS*CDP];
__device__ half  g_khh[(size_t)CB*CH*CS*CDP];
__device__ half  g_vhh[(size_t)CB*CH*CS*CDP];
__device__ float g_res[(size_t)CBS*CD];
__device__ half  g_wqkvh[(size_t)CD*CFF];
__device__ float g_bqkv[CFF];
__device__ half  g_wrh [(size_t)11664000];
#define WR_WO 0
#define WR_W1 1166400
#define WR_W3 4665600
#define WR_W2 8164800

enum { EPI_NONE=0, EPI_SCALE=1, EPI_BIAS=2, EPI_BIAS_RES=3, EPI_SWIGLU=4 };

__device__ __forceinline__ void cp_async16(void* smem, const void* gmem, bool pred)
{
    unsigned saddr = (unsigned)__cvta_generic_to_shared(smem);
    int sz = pred ? 16 : 0;
    asm volatile("cp.async.cg.shared.global [%0], [%1], 16, %2;\n"
                 :: "r"(saddr), "l"(gmem), "r"(sz));
}
__device__ __forceinline__ void cp_commit() { asm volatile("cp.async.commit_group;\n"); }

__device__ __forceinline__ void mma_f16(float* d,
    unsigned a0, unsigned a1, unsigned a2, unsigned a3,
    unsigned b0, unsigned b1)
{
    asm volatile("mma.sync.aligned.m16n8k16.row.col.f32.f16.f16.f32 "
                 "{%0,%1,%2,%3}, {%4,%5,%6,%7}, {%8,%9}, {%0,%1,%2,%3};"
                 : "+f"(d[0]), "+f"(d[1]), "+f"(d[2]), "+f"(d[3])
                 : "r"(a0), "r"(a1), "r"(a2), "r"(a3), "r"(b0), "r"(b1));
}

__device__ __forceinline__ void ldsm4t(unsigned& r0, unsigned& r1,
                                       unsigned& r2, unsigned& r3, const half* p)
{
    unsigned addr = (unsigned)__cvta_generic_to_shared(p);
    asm volatile("ldmatrix.sync.aligned.m8n8.x4.trans.shared.b16 {%0,%1,%2,%3}, [%4];"
                 : "=r"(r0), "=r"(r1), "=r"(r2), "=r"(r3) : "r"(addr));
}

__device__ __forceinline__ void store4(float* p, float4 v)
{
    *reinterpret_cast<float4*>(p) = v;
}
__device__ __forceinline__ void store4(half* p, float4 v)
{
    half2* h = reinterpret_cast<half2*>(p);
    h[0] = __floats2half2_rn(v.x, v.y);
    h[1] = __floats2half2_rn(v.z, v.w);
}
__device__ __forceinline__ float4 load4aux(const float* p)
{
    return *reinterpret_cast<const float4*>(p);
}
__device__ __forceinline__ float4 load4aux(const half* p)
{
    const half2* h = reinterpret_cast<const half2*>(p);
    float2 a = __half22float2(h[0]);
    float2 b = __half22float2(h[1]);
    return make_float4(a.x, a.y, b.x, b.y);
}

// ------ FP16 GEMM (R15 winner): 128x128, 32x64 warp tile, BK=32, 4-stage ----
#define ALDH 40
#define BLDH 136
#define CLD 24
#define STG_A_H (128*ALDH)
#define STG_B_H (32*BLDH)
#define STG_H (STG_A_H+STG_B_H)
#define SMEM_BYTES (4*STG_H*2)      // 75776 B

template<int EPI, typename OutT, typename AuxT>
__global__ __launch_bounds__(256, 2)
void gemm_h(const half* __restrict__ A, int lda,
            const half* __restrict__ Bm, int ldb,
            OutT* __restrict__ C, int ldc,
            const float* __restrict__ bias,
            const AuxT* __restrict__ aux, int ldx,
            int M, int N, int K)
{
    const int m0 = blockIdx.y * 128;
    const int n0 = blockIdx.x * 128;
    const int kEnd  = K;
    const int nIter = (kEnd + 31) >> 5;

    extern __shared__ __align__(16) char smem_raw[];
    half* smem_h = reinterpret_cast<half*>(smem_raw);

    const int tid = threadIdx.x;
    const int wid = tid >> 5;
    const int lane = tid & 31;
    const int warp_m = wid & 3;
    const int warp_n = wid >> 2;

    const int aRow = tid >> 1;
    const int aC0  = (tid & 1) * 16;
    const int bRow = tid >> 3;
    const int bC0  = (tid & 7) * 16;

    const bool aRowOk = (m0 + aRow) < M;
    const half* aBase = A + (long)(m0 + aRow) * lda + aC0;
    const half* bBase = Bm + (long)bRow * ldb + n0 + bC0;
    const bool bColOk  = (n0 + bC0) < N;
    const bool bColOk8 = (n0 + bC0 + 8) < N;

    wmma::fragment<wmma::accumulator, 16, 16, 16, float> acc[2][4];
    #pragma unroll
    for (int i = 0; i < 2; i++)
        #pragma unroll
        for (int j = 0; j < 4; j++) wmma::fill_fragment(acc[i][j], 0.f);

    auto issue = [&](int it, int buf) {
        const int k0 = it << 5;
        half* as = smem_h + buf * STG_H;
        half* bs = as + STG_A_H;
        cp_async16(&as[aRow * ALDH + aC0],     aBase + k0,     aRowOk && (k0 + aC0     < kEnd));
        cp_async16(&as[aRow * ALDH + aC0 + 8], aBase + k0 + 8, aRowOk && (k0 + aC0 + 8 < kEnd));
        const bool rOk = (k0 + bRow) < kEnd;
        cp_async16(&bs[bRow * BLDH + bC0],     bBase + (long)k0 * ldb,     rOk && bColOk);
        cp_async16(&bs[bRow * BLDH + bC0 + 8], bBase + (long)k0 * ldb + 8, rOk && bColOk8);
    };

    issue(0, 0); cp_commit();
    if (nIter > 1) { issue(1, 1); cp_commit(); }
    if (nIter > 2) { issue(2, 2); cp_commit(); }

    for (int it = 0; it < nIter; it++) {
        const int buf = it & 3;
        if (it + 2 < nIter)      asm volatile("cp.async.wait_group 2;\n");
        else if (it + 1 < nIter) asm volatile("cp.async.wait_group 1;\n");
        else                     asm volatile("cp.async.wait_group 0;\n");
        __syncthreads();
        if (it + 3 < nIter) { issue(it + 3, (it + 3) & 3); cp_commit(); }

        const half* as = smem_h + buf * STG_H;
        const half* bs = as + STG_A_H;
        #pragma unroll
        for (int kk = 0; kk < 32; kk += 16) {
            wmma::fragment<wmma::matrix_a, 16, 16, 16, half, wmma::row_major> af[2];
            #pragma unroll
            for (int i = 0; i < 2; i++)
                wmma::load_matrix_sync(af[i], &as[(warp_m * 32 + i * 16) * ALDH + kk], ALDH);
            #pragma unroll
            for (int j = 0; j < 4; j++) {
                wmma::fragment<wmma::matrix_b, 16, 16, 16, half, wmma::row_major> bf;
                wmma::load_matrix_sync(bf, &bs[kk * BLDH + warp_n * 64 + j * 16], BLDH);
                wmma::mma_sync(acc[0][j], af[0], bf, acc[0][j]);
                wmma::mma_sync(acc[1][j], af[1], bf, acc[1][j]);
            }
        }
    }
    __syncthreads();

    float* fstage = reinterpret_cast<float*>(smem_raw) + wid * 16 * CLD;
    const int er  = lane >> 1;
    const int ec0 = (lane & 1) * 8;
    #pragma unroll
    for (int i = 0; i < 2; i++) {
        #pragma unroll
        for (int j = 0; j < 4; j++) {
            wmma::store_matrix_sync(fstage, acc[i][j], CLD, wmma::mem_row_major);
            __syncwarp();
            const int gr = m0 + warp_m * 32 + i * 16 + er;
            const int gcb = n0 + warp_n * 64 + j * 16 + ec0;
            if (gr < M) {
                #pragma unroll
                for (int h4 = 0; h4 < 2; h4++) {
                    const int gc = gcb + h4 * 4;
                    if (gc + 3 < N) {
                        float4 v = *reinterpret_cast<const float4*>(&fstage[er * CLD + ec0 + h4 * 4]);
                        if (EPI == EPI_BIAS) {
                            float4 bv = *reinterpret_cast<const float4*>(&bias[gc]);
                            v.x += bv.x; v.y += bv.y; v.z += bv.z; v.w += bv.w;
                        }
                        if (EPI == EPI_BIAS_RES) {
                            float4 bv = *reinterpret_cast<const float4*>(&bias[gc]);
                            float4 av = load4aux(&aux[(long)gr * ldx + gc]);
                            v.x += bv.x + av.x; v.y += bv.y + av.y;
                            v.z += bv.z + av.z; v.w += bv.w + av.w;
                        }
                        if (EPI == EPI_SWIGLU) {
                            float4 bv = *reinterpret_cast<const float4*>(&bias[gc]);
                            float4 hv = load4aux(&aux[(long)gr * ldx + gc]);
                            v.x = (hv.x / (1.f + __expf(-hv.x))) * (v.x + bv.x);
                            v.y = (hv.y / (1.f + __expf(-hv.y))) * (v.y + bv.y);
                            v.z = (hv.z / (1.f + __expf(-hv.z))) * (v.z + bv.z);
                            v.w = (hv.w / (1.f + __expf(-hv.w))) * (v.w + bv.w);
                        }
                        store4(&C[(long)gr * ldc + gc], v);
                    }
                }
            }
            __syncwarp();
        }
    }
}

// ------------- flash attention: fp16 m16n8k16, ldmatrix.trans PV -----------
#define FQ 128
#define FN 64
#define QLDH 104
#define FLASH_SMEM ((FQ*QLDH + 2*FN*QLDH)*2)   // 53248 B

__global__ __launch_bounds__(256, 2)
void flash_k(const half* __restrict__ qh, const half* __restrict__ kh,
             const half* __restrict__ vh, half* __restrict__ attn, float iscale)
{
    const int zi = blockIdx.y;
    const int iT = (int)gridDim.x - 1 - (int)blockIdx.x;
    const int i0 = iT * FQ;
    const int tid = threadIdx.x;
    const int wid = tid >> 5;
    const int lane = tid & 31;
    const int g = lane >> 2;
    const int t = lane & 3;

    const half* Qp = qh + (long)zi * CS * CDP;
    const half* Kp = kh + (long)zi * CS * CDP;
    const half* Vp = vh + (long)zi * CS * CDP;

    extern __shared__ __align__(16) half smh[];
    half* Qs = smh;
    half* Ks = smh + FQ * QLDH;
    half* Vs = Ks + FN * QLDH;

    for (int tt = tid; tt < FQ * 12; tt += 256) {
        int r = tt / 12, c8 = (tt % 12) * 8;
        cp_async16(&Qs[r * QLDH + c8], Qp + (long)(i0 + r) * CDP + c8, (i0 + r) < CS);
    }
    cp_commit();

    float oacc[12][4];
    #pragma unroll
    for (int n = 0; n < 12; n++)
        #pragma unroll
        for (int s = 0; s < 4; s++) oacc[n][s] = 0.f;
    float m0 = -1e30f, m1 = -1e30f, l0 = 0.f, l1 = 0.f;

    const int rw = wid * 16;
    const int row0 = i0 + rw + g;
    const int row1 = row0 + 8;
    const int jn = (min(CS, i0 + FQ) + FN - 1) / FN;

    asm volatile("cp.async.wait_group 0;\n");
    __syncthreads();

    for (int j = 0; j < jn; j++) {
        const int j0 = j * FN;
        __syncthreads();
        for (int tt = tid; tt < FN * 12; tt += 256) {
            int r = tt / 12, c8 = (tt % 12) * 8;
            cp_async16(&Ks[r * QLDH + c8], Kp + (long)(j0 + r) * CDP + c8, (j0 + r) < CS);
        }
        cp_commit();
        for (int tt = tid; tt < FN * 12; tt += 256) {
            int r = tt / 12, c8 = (tt % 12) * 8;
            cp_async16(&Vs[r * QLDH + c8], Vp + (long)(j0 + r) * CDP + c8, (j0 + r) < CS);
        }
        cp_commit();
        asm volatile("cp.async.wait_group 1;\n");
        __syncthreads();

        const bool active = (j0 <= i0 + rw + 15);
        float sacc[8][4];

        if (active) {
            #pragma unroll
            for (int n = 0; n < 8; n++)
                #pragma unroll
                for (int s = 0; s < 4; s++) sacc[n][s] = 0.f;

            #pragma unroll
            for (int kf = 0; kf < 6; kf++) {
                const int kc = kf * 16;
                unsigned a0 = *reinterpret_cast<const unsigned*>(&Qs[(rw + g)     * QLDH + kc + 2 * t]);
                unsigned a1 = *reinterpret_cast<const unsigned*>(&Qs[(rw + g + 8) * QLDH + kc + 2 * t]);
                unsigned a2 = *reinterpret_cast<const unsigned*>(&Qs[(rw + g)     * QLDH + kc + 2 * t + 8]);
                unsigned a3 = *reinterpret_cast<const unsigned*>(&Qs[(rw + g + 8) * QLDH + kc + 2 * t + 8]);
                #pragma unroll
                for (int nf = 0; nf < 8; nf++) {
                    unsigned b0 = *reinterpret_cast<const unsigned*>(&Ks[(nf * 8 + g) * QLDH + kc + 2 * t]);
                    unsigned b1 = *reinterpret_cast<const unsigned*>(&Ks[(nf * 8 + g) * QLDH + kc + 2 * t + 8]);
                    mma_f16(sacc[nf], a0, a1, a2, a3, b0, b1);
                }
            }

            float rmax0 = -1e30f, rmax1 = -1e30f;
            #pragma unroll
            for (int nf = 0; nf < 8; nf++) {
                const int c0 = j0 + nf * 8 + 2 * t;
                float s0 = sacc[nf][0] * iscale; if (c0     > row0) s0 = -1e30f;
                float s1 = sacc[nf][1] * iscale; if (c0 + 1 > row0) s1 = -1e30f;
                float s2 = sacc[nf][2] * iscale; if (c0     > row1) s2 = -1e30f;
                float s3 = sacc[nf][3] * iscale; if (c0 + 1 > row1) s3 = -1e30f;
                sacc[nf][0] = s0; sacc[nf][1] = s1; sacc[nf][2] = s2; sacc[nf][3] = s3;
                rmax0 = fmaxf(rmax0, fmaxf(s0, s1));
                rmax1 = fmaxf(rmax1, fmaxf(s2, s3));
            }
            rmax0 = fmaxf(rmax0, __shfl_xor_sync(0xffffffffu, rmax0, 1));
            rmax0 = fmaxf(rmax0, __shfl_xor_sync(0xffffffffu, rmax0, 2));
            rmax1 = fmaxf(rmax1, __shfl_xor_sync(0xffffffffu, rmax1, 1));
            rmax1 = fmaxf(rmax1, __shfl_xor_sync(0xffffffffu, rmax1, 2));

            const float mn0 = fmaxf(m0, rmax0);
            const float mn1 = fmaxf(m1, rmax1);
            const float al0 = __expf(m0 - mn0);
            const float al1 = __expf(m1 - mn1);
            float ps0 = 0.f, ps1 = 0.f;
            #pragma unroll
            for (int nf = 0; nf < 8; nf++) {
                float p0 = __half2float(__float2half_rn(__expf(sacc[nf][0] - mn0)));
                float p1 = __half2float(__float2half_rn(__expf(sacc[nf][1] - mn0)));
                float p2 = __half2float(__float2half_rn(__expf(sacc[nf][2] - mn1)));
                float p3 = __half2float(__float2half_rn(__expf(sacc[nf][3] - mn1)));
                sacc[nf][0] = p0; sacc[nf][1] = p1; sacc[nf][2] = p2; sacc[nf][3] = p3;
                ps0 += p0 + p1; ps1 += p2 + p3;
            }
            ps0 += __shfl_xor_sync(0xffffffffu, ps0, 1);
            ps0 += __shfl_xor_sync(0xffffffffu, ps0, 2);
            ps1 += __shfl_xor_sync(0xffffffffu, ps1, 1);
            ps1 += __shfl_xor_sync(0xffffffffu, ps1, 2);
            l0 = l0 * al0 + ps0;  m0 = mn0;
            l1 = l1 * al1 + ps1;  m1 = mn1;

            #pragma unroll
            for (int n = 0; n < 12; n++) {
                oacc[n][0] *= al0; oacc[n][1] *= al0;
                oacc[n][2] *= al1; oacc[n][3] *= al1;
            }
        }

        asm volatile("cp.async.wait_group 0;\n");
        __syncthreads();

        if (active) {
            #pragma unroll
            for (int kf = 0; kf < 4; kf++) {
                const int kc = kf * 16;
                half2 h0 = __floats2half2_rn(sacc[2*kf][0],     sacc[2*kf][1]);
                half2 h1 = __floats2half2_rn(sacc[2*kf][2],     sacc[2*kf][3]);
                half2 h2 = __floats2half2_rn(sacc[2*kf + 1][0], sacc[2*kf + 1][1]);
                half2 h3 = __floats2half2_rn(sacc[2*kf + 1][2], sacc[2*kf + 1][3]);
                unsigned a0 = *reinterpret_cast<unsigned*>(&h0);
                unsigned a1 = *reinterpret_cast<unsigned*>(&h1);
                unsigned a2 = *reinterpret_cast<unsigned*>(&h2);
                unsigned a3 = *reinterpret_cast<unsigned*>(&h3);
                const half* vrow = &Vs[(kc + (lane & 15)) * QLDH + 8 * (lane >> 4)];
                #pragma unroll
                for (int nfp = 0; nfp < 6; nfp++) {
                    unsigned b0a, b1a, b0b, b1b;
                    ldsm4t(b0a, b1a, b0b, b1b, vrow + nfp * 16);
                    mma_f16(oacc[2 * nfp],     a0, a1, a2, a3, b0a, b1a);
                    mma_f16(oacc[2 * nfp + 1], a0, a1, a2, a3, b0b, b1b);
                }
            }
        }
    }

    const int b = zi / CH, h = zi - b * CH;
    const float il0 = (l0 > 0.f) ? 1.f / l0 : 0.f;
    const float il1 = (l1 > 0.f) ? 1.f / l1 : 0.f;
    #pragma unroll
    for (int nf = 0; nf < 12; nf++) {
        const int c0 = nf * 8 + 2 * t;
        if (c0 < CDK) {
            if (row0 < CS) {
                half2 v = __floats2half2_rn(oacc[nf][0] * il0, oacc[nf][1] * il0);
                *reinterpret_cast<half2*>(&attn[((long)b * CS + row0) * CD + h * CDK + c0]) = v;
            }
            if (row1 < CS) {
                half2 v = __floats2half2_rn(oacc[nf][2] * il1, oacc[nf][3] * il1);
                *reinterpret_cast<half2*>(&attn[((long)b * CS + row1) * CD + h * CDK + c0]) = v;
            }
        }
    }
}

// -------- single-launch f32 -> fp16 conversion for all 4 weights ------------
__global__ __launch_bounds__(256)
void cvt_all_k(const float* __restrict__ Wo, const float* __restrict__ W1,
               const float* __restrict__ W3, const float* __restrict__ W2,
               half* __restrict__ d)
{
    const int N_WO = 291600, N_W1 = 874800;
    int i = blockIdx.x * 256 + threadIdx.x;
    const float* s;
    size_t off;
    if (i < N_WO)                   { s = Wo; off = 0;                  }
    else if (i < N_WO + N_W1)       { s = W1; off = N_WO;               }
    else if (i < N_WO + 2 * N_W1)   { s = W3; off = N_WO + N_W1;        }
    else if (i < N_WO + 3 * N_W1)   { s = W2; off = N_WO + 2 * N_W1;    }
    else return;
    size_t li = i - off;
    float4 v = reinterpret_cast<const float4*>(s)[li];
    half2* p = reinterpret_cast<half2*>(d + (off + li) * 4);
    p[0] = __floats2half2_rn(v.x, v.y);
    p[1] = __floats2half2_rn(v.z, v.w);
}

// ---------------- pack Wq|Wk|Wv -> fp16 [1080][3240] ----------------
__global__ __launch_bounds__(256)
void pack_qkv_k(const float* __restrict__ Wq, const float* __restrict__ Wk,
                const float* __restrict__ Wv,
                const float* __restrict__ bq, const float* __restrict__ bk,
                const float* __restrict__ bv,
                half* __restrict__ W, float* __restrict__ b)
{
    const int NW4 = CD * (CD / 4);
    long idx = (long)blockIdx.x * 256 + threadIdx.x;
    if (idx < NW4) {
        int r = (int)(idx / (CD / 4));
        int c = (int)(idx % (CD / 4)) * 4;
        float4 vq = *reinterpret_cast<const float4*>(Wq + (long)r * CD + c);
        float4 vk = *reinterpret_cast<const float4*>(Wk + (long)r * CD + c);
        float4 vv = *reinterpret_cast<const float4*>(Wv + (long)r * CD + c);
        half2* pq = reinterpret_cast<half2*>(W + (long)r * CFF + c);
        half2* pk = reinterpret_cast<half2*>(W + (long)r * CFF + CD + c);
        half2* pv = reinterpret_cast<half2*>(W + (long)r * CFF + 2 * CD + c);
        pq[0] = __floats2half2_rn(vq.x, vq.y); pq[1] = __floats2half2_rn(vq.z, vq.w);
        pk[0] = __floats2half2_rn(vk.x, vk.y); pk[1] = __floats2half2_rn(vk.z, vk.w);
        pv[0] = __floats2half2_rn(vv.x, vv.y); pv[1] = __floats2half2_rn(vv.z, vv.w);
    } else if (idx < NW4 + CD / 4) {
        int c = (int)(idx - NW4) * 4;
        *reinterpret_cast<float4*>(b + c)          = *reinterpret_cast<const float4*>(bq + c);
        *reinterpret_cast<float4*>(b + CD + c)     = *reinterpret_cast<const float4*>(bk + c);
        *reinterpret_cast<float4*>(b + 2 * CD + c) = *reinterpret_cast<const float4*>(bv + c);
    }
}

// ---------------- layernorm (vectorized) -> fp16 output ----------------
__global__ __launch_bounds__(256)
void ln_k(const float* __restrict__ x, const float* __restrict__ g,
          const float* __restrict__ b, half* __restrict__ y)
{
    const long row = blockIdx.x;
    const float* xr = x + row * CD;
    half* yr = y + row * CD;
    const int tid = threadIdx.x;

    float4 v0 = reinterpret_cast<const float4*>(xr)[tid];
    float4 v1 = make_float4(0.f, 0.f, 0.f, 0.f);
    const bool has2 = (tid + 256) < (CD / 4);
    if (has2) v1 = reinterpret_cast<const float4*>(xr)[tid + 256];

    float s  = v0.x + v0.y + v0.z + v0.w + v1.x + v1.y + v1.z + v1.w;
    float s2 = v0.x*v0.x + v0.y*v0.y + v0.z*v0.z + v0.w*v0.w
             + v1.x*v1.x + v1.y*v1.y + v1.z*v1.z + v1.w*v1.w;

    __shared__ float rs[8], rs2[8];
    __shared__ float bm, br;
    #pragma unroll
    for (int o = 16; o; o >>= 1) {
        s  += __shfl_xor_sync(0xffffffffu, s,  o);
        s2 += __shfl_xor_sync(0xffffffffu, s2, o);
    }
    if ((tid & 31) == 0) { rs[tid >> 5] = s; rs2[tid >> 5] = s2; }
    __syncthreads();
    if (tid < 8) {
        float a = rs[tid], a2 = rs2[tid];
        #pragma unroll
        for (int o = 4; o; o >>= 1) {
            a  += __shfl_xor_sync(0xffu, a,  o);
            a2 += __shfl_xor_sync(0xffu, a2, o);
        }
        if (tid == 0) {
            float mean = a / CD;
            float var  = a2 / CD - mean * mean;
            bm = mean;
            br = rsqrtf(var + 1e-5f);
        }
    }
    __syncthreads();
    const float mean = bm, rstd = br;

    {
        float4 gv = reinterpret_cast<const float4*>(g)[tid];
        float4 bv = reinterpret_cast<const float4*>(b)[tid];
        float4 o;
        o.x = (v0.x - mean) * rstd * gv.x + bv.x;
        o.y = (v0.y - mean) * rstd * gv.y + bv.y;
        o.z = (v0.z - mean) * rstd * gv.z + bv.z;
        o.w = (v0.w - mean) * rstd * gv.w + bv.w;
        store4(&yr[tid * 4], o);
    }
    if (has2) {
        float4 gv = reinterpret_cast<const float4*>(g)[tid + 256];
        float4 bv = reinterpret_cast<const float4*>(b)[tid + 256];
        float4 o;
        o.x = (v1.x - mean) * rstd * gv.x + bv.x;
        o.y = (v1.y - mean) * rstd * gv.y + bv.y;
        o.z = (v1.z - mean) * rstd * gv.z + bv.z;
        o.w = (v1.w - mean) * rstd * gv.w + bv.w;
        store4(&yr[(tid + 256) * 4], o);
    }
}

// -------- RoPE + repack from fp16 fused QKV to fp16 [B*H, S, 96] ------------
__global__ __launch_bounds__(256)
void rope_repack_k(const half* __restrict__ qkv,
                   const float* __restrict__ ct, const float* __restrict__ st,
                   half* __restrict__ qh, half* __restrict__ kh,
                   half* __restrict__ vh)
{
    const long total = (long)CB * CH * CS * 48;
    long idx = (long)blockIdx.x * 256 + threadIdx.x;
    if (idx >= total) return;
    const int d = (int)(idx % 48);  idx /= 48;
    const int s = (int)(idx % CS);  idx /= CS;
    const int h = (int)(idx % CH);
    const int b = (int)(idx / CH);

    const long src = ((long)b * CS + s) * CFF + h * CDK;
    const long dst = (((long)b * CH + h) * CS + s) * CDP;

    if (d < 45) {
        const float c1 = ct[s * CDK + d],      s1 = st[s * CDK + d];
        const float c2 = ct[s * CDK + d + 45], s2 = st[s * CDK + d + 45];
        float q1 = __half2float(qkv[src + d]),      q2 = __half2float(qkv[src + d + 45]);
        qh[dst + d]      = __float2half(q1 * c1 - q2 * s1);
        qh[dst + d + 45] = __float2half(q2 * c2 + q1 * s2);
        float k1 = __half2float(qkv[src + CD + d]), k2 = __half2float(qkv[src + CD + d + 45]);
        kh[dst + d]      = __float2half(k1 * c1 - k2 * s1);
        kh[dst + d + 45] = __float2half(k2 * c2 + k1 * s2);
        vh[dst + d]      = qkv[src + 2 * CD + d];
        vh[dst + d + 45] = qkv[src + 2 * CD + d + 45];
    } else {
        const int p = 90 + 2 * (d - 45);
        qh[dst + p] = __float2half(0.f); qh[dst + p + 1] = __float2half(0.f);
        kh[dst + p] = __float2half(0.f); kh[dst + p + 1] = __float2half(0.f);
        vh[dst + p] = __float2half(0.f); vh[dst + p + 1] = __float2half(0.f);
    }
}

// ---------------- host launch ----------------
extern "C" void kernel_launch(void* const* d_in, const int* in_sizes, int n_in,
                              void* d_out, int out_size)
{
    const float* x    = (const float*)d_in[0];
    const float* Wq   = (const float*)d_in[2];
    const float* bq   = (const float*)d_in[3];
    const float* Wk   = (const float*)d_in[4];
    const float* bk   = (const float*)d_in[5];
    const float* Wv   = (const float*)d_in[6];
    const float* bv   = (const float*)d_in[7];
    const float* Wo   = (const float*)d_in[8];
    const float* bo   = (const float*)d_in[9];
    const float* W1   = (const float*)d_in[10];
    const float* b1   = (const float*)d_in[11];
    const float* W2   = (const float*)d_in[12];
    const float* b2   = (const float*)d_in[13];
    const float* W3   = (const float*)d_in[14];
    const float* b3   = (const float*)d_in[15];
    const float* ln1g = (const float*)d_in[16];
    const float* ln1b = (const float*)d_in[17];
    const float* ln2g = (const float*)d_in[18];
    const float* ln2b = (const float*)d_in[19];
    const float* rc   = (const float*)d_in[20];
    const float* rs   = (const float*)d_in[21];
    float* out = (float*)d_out;

    half *x2h, *qkvh, *h1h, *attnh, *wqkvh, *wrh, *qhh, *khh, *vhh;
    float *res, *bqkv;
    cudaGetSymbolAddress((void**)&x2h,   g_x2h);
    cudaGetSymbolAddress((void**)&qkvh,  g_qkvh);
    cudaGetSymbolAddress((void**)&h1h,   g_h1h);
    cudaGetSymbolAddress((void**)&attnh, g_attnh);
    cudaGetSymbolAddress((void**)&qhh,   g_qhh);
    cudaGetSymbolAddress((void**)&khh,   g_khh);
    cudaGetSymbolAddress((void**)&vhh,   g_vhh);
    cudaGetSymbolAddress((void**)&res,   g_res);
    cudaGetSymbolAddress((void**)&wqkvh, g_wqkvh);
    cudaGetSymbolAddress((void**)&bqkv,  g_bqkv);
    cudaGetSymbolAddress((void**)&wrh,   g_wrh);

    cudaFuncSetAttribute((const void*)gemm_h<EPI_BIAS, half, float>,
                         cudaFuncAttributeMaxDynamicSharedMemorySize, SMEM_BYTES);
    cudaFuncSetAttribute((const void*)gemm_h<EPI_BIAS_RES, float, float>,
                         cudaFuncAttributeMaxDynamicSharedMemorySize, SMEM_BYTES);
    cudaFuncSetAttribute((const void*)gemm_h<EPI_SWIGLU, half, half>,
                         cudaFuncAttributeMaxDynamicSharedMemorySize, SMEM_BYTES);
    cudaFuncSetAttribute((const void*)flash_k,
                         cudaFuncAttributeMaxDynamicSharedMemorySize, FLASH_SMEM);

    const float iscale = 1.f / sqrtf((float)CDK);

    // 0) fp16 weights (single launch) + pack QKV
    cvt_all_k<<<(2916000 + 255) / 256, 256>>>(Wo, W1, W3, W2, wrh);
    {
        int total = CD * (CD / 4) + CD / 4;
        pack_qkv_k<<<(total + 255) / 256, 256>>>(Wq, Wk, Wv, bq, bk, bv, wqkvh, bqkv);
    }

    // 1) LN1 -> fp16
    ln_k<<<CBS, 256>>>(x, ln1g, ln1b, x2h);

    // 2) fused QKV projection
    dim3 gQKV((CFF + 127) / 128, (CBS + 127) / 128, 1);
    gemm_h<EPI_BIAS, half, float><<<gQKV, 256, SMEM_BYTES>>>(
        x2h, CD, wqkvh, CFF, qkvh, CFF, bqkv, (const float*)nullptr, 0, CBS, CFF, CD);

    // 3) RoPE + repack
    {
        long total = (long)CB * CH * CS * 48;
        rope_repack_k<<<(unsigned)((total + 255) / 256), 256>>>(qkvh, rc, rs, qhh, khh, vhh);
    }

    // 4) flash attention
    {
        dim3 g((CS + FQ - 1) / FQ, CB * CH);
        flash_k<<<g, 256, FLASH_SMEM>>>(qhh, khh, vhh, attnh, iscale);
    }

    // 5) O-projection + bias + residual(x) -> f32 res
    dim3 gD((CD + 127) / 128, (CBS + 127) / 128, 1);
    gemm_h<EPI_BIAS_RES, float, float><<<gD, 256, SMEM_BYTES>>>(
        attnh, CD, wrh + WR_WO, CD, res, CD, bo, x, CD, CBS, CD, CD);

    // 6) LN2 -> fp16
    ln_k<<<CBS, 256>>>(res, ln2g, ln2b, x2h);

    // 7) h1 = x2@W1 + b1
    dim3 gF((CFF + 127) / 128, (CBS + 127) / 128, 1);
    gemm_h<EPI_BIAS, half, float><<<gF, 256, SMEM_BYTES>>>(
        x2h, CD, wrh + WR_W1, CFF, h1h, CFF, b1, (const float*)nullptr, 0, CBS, CFF, CD);

    // 8) h1 = silu(h1) * (x2@W3 + b3)
    gemm_h<EPI_SWIGLU, half, half><<<gF, 256, SMEM_BYTES>>>(
        x2h, CD, wrh + WR_W3, CFF, h1h, CFF, b3, h1h, CFF, CBS, CFF, CD);

    // 9) out = res + h1@W2 + b2
    gemm_h<EPI_BIAS_RES, float, float><<<gD, 256, SMEM_BYTES>>>(
        h1h, CFF, wrh + WR_W2, CD, out, CD, b2, res, CD, CBS, CD, CFF);
}